// round 15
// baseline (speedup 1.0000x reference)
#include <cuda_runtime.h>
#include <cuda_bf16.h>
#include <cuda_fp16.h>
#include <math.h>
#include <stdint.h>

#define HH 128
#define WW 128
#define HW 16384
#define BB 2

// ==================== helpers ====================
__device__ __forceinline__ uint32_t smem_u32(const void* p) {
    uint32_t a;
    asm("{ .reg .u64 t; cvta.to.shared.u64 t, %1; cvt.u32.u64 %0, t; }" : "=r"(a) : "l"(p));
    return a;
}
__device__ __forceinline__ void ldsm_x4(uint32_t* r, uint32_t addr) {
    asm volatile("ldmatrix.sync.aligned.m8n8.x4.shared.b16 {%0,%1,%2,%3}, [%4];"
        : "=r"(r[0]), "=r"(r[1]), "=r"(r[2]), "=r"(r[3]) : "r"(addr));
}
__device__ __forceinline__ void mma_bf16(float* c, const uint32_t* a, const uint32_t* b) {
    asm volatile(
        "mma.sync.aligned.m16n8k16.row.col.f32.bf16.bf16.f32 "
        "{%0,%1,%2,%3}, {%4,%5,%6,%7}, {%8,%9}, {%0,%1,%2,%3};"
        : "+f"(c[0]), "+f"(c[1]), "+f"(c[2]), "+f"(c[3])
        : "r"(a[0]), "r"(a[1]), "r"(a[2]), "r"(a[3]), "r"(b[0]), "r"(b[1]));
}
__device__ __forceinline__ void mma_f16(float* c, const uint32_t* a, const uint32_t* b) {
    asm volatile(
        "mma.sync.aligned.m16n8k16.row.col.f32.f16.f16.f32 "
        "{%0,%1,%2,%3}, {%4,%5,%6,%7}, {%8,%9}, {%0,%1,%2,%3};"
        : "+f"(c[0]), "+f"(c[1]), "+f"(c[2]), "+f"(c[3])
        : "r"(a[0]), "r"(a[1]), "r"(a[2]), "r"(a[3]), "r"(b[0]), "r"(b[1]));
}
__device__ __forceinline__ uint32_t pack_bf(float v) {
    __nv_bfloat16 h = __float2bfloat16(v);
    float hf = __bfloat162float(h);
    __nv_bfloat16 l = __float2bfloat16(v - hf);
    return (uint32_t)__bfloat16_as_ushort(h) | ((uint32_t)__bfloat16_as_ushort(l) << 16);
}
#define CP_ASYNC16(dst, src, sz) \
    asm volatile("cp.async.cg.shared.global [%0], [%1], 16, %2;" \
        :: "r"(dst), "l"(src), "r"(sz))
#define CP_COMMIT()  asm volatile("cp.async.commit_group;" ::: "memory")
#define CP_WAIT0()   asm volatile("cp.async.wait_group 0;" ::: "memory")

// ==================== scratch globals ====================
__device__ __align__(16) uint16_t g_in0h[BB*4*HW*64], g_in0l[BB*4*HW*64];
__device__ __align__(16) uint16_t g_h1h [BB*HW*64],   g_h1l [BB*HW*64];
__device__ __align__(16) uint16_t g_h2h [BB*HW*64],   g_h2l [BB*HW*64];
__device__ __align__(16) uint16_t g_h3h [BB*HW*64],   g_h3l [BB*HW*64];
__device__ float4   g_offm[BB*144*HW];    // {oy, ox, mask, pad}
__device__ __align__(16) __half g_xt[BB*128*HW];  // x fp16 channels-last [b][g][pix][8]
// dcn weights fp16 2-plane, mma layout [g][o][88], j=k*8+c, 72..87 zero
__device__ __align__(16) __half g_wth[16*64*88], g_wtl[16*64*88];
// conv weight tiles: [j][CoutP rows][72 cols] bf16, zero-padded
__device__ __align__(16) uint16_t g_w1h[36*64*72],  g_w1l[36*64*72];
__device__ __align__(16) uint16_t g_w2h[9*64*72],   g_w2l[9*64*72];
__device__ __align__(16) uint16_t g_w3h[9*64*72],   g_w3l[9*64*72];
__device__ __align__(16) uint16_t g_w4h[9*448*72],  g_w4l[9*448*72];

// ==================== prep kernels ====================
__global__ __launch_bounds__(256) void pack_in0_k(
    const float* __restrict__ ef, const float* __restrict__ f1, const float* __restrict__ f2)
{
    __shared__ uint32_t S[64*65];
    int cc = blockIdx.y, b = blockIdx.z;
    int pix0 = blockIdx.x * 64;
    int t = threadIdx.x;
    for (int i = t; i < 4096; i += 256) {
        int ch = i >> 6, px = i & 63;
        int g = cc*64 + ch;
        float v = 0.f;
        if (g < 192)      v = ef[((size_t)b*192 + g)*HW + pix0 + px];
        else if (g < 194) v = f1[((size_t)b*2 + (g-192))*HW + pix0 + px];
        else if (g < 196) v = f2[((size_t)b*2 + (g-194))*HW + pix0 + px];
        S[ch*65 + px] = pack_bf(v);
    }
    __syncthreads();
    for (int i = t; i < 2048; i += 256) {
        int px = i >> 5, c2 = i & 31;
        uint32_t u0 = S[(c2*2)*65 + px];
        uint32_t u1 = S[(c2*2+1)*65 + px];
        size_t base = ((((size_t)b*4 + cc)*HW + pix0 + px) << 6) >> 1;
        ((uint32_t*)g_in0h)[base + c2] = (u0 & 0xffffu) | (u1 << 16);
        ((uint32_t*)g_in0l)[base + c2] = (u0 >> 16) | (u1 & 0xffff0000u);
    }
}

__global__ __launch_bounds__(256) void wprep_k(
    const float* __restrict__ w, int Cin, int CoutR, int CoutP, int J,
    uint16_t* __restrict__ dh, uint16_t* __restrict__ dl)
{
    int idx = blockIdx.x*256 + threadIdx.x;
    if (idx >= J*CoutP*72) return;
    int col = idx % 72;
    int o   = (idx / 72) % CoutP;
    int j   = idx / (72*CoutP);
    int cc = j / 9, kk = j % 9;
    int cin = cc*64 + col;
    float v = (col < 64 && cin < Cin && o < CoutR) ? w[((size_t)o*Cin + cin)*9 + kk] : 0.f;
    __nv_bfloat16 h = __float2bfloat16(v);
    float hf = __bfloat162float(h);
    __nv_bfloat16 l = __float2bfloat16(v - hf);
    dh[idx] = __bfloat16_as_ushort(h);
    dl[idx] = __bfloat16_as_ushort(l);
}

__global__ __launch_bounds__(256) void transp_x_k(const float* __restrict__ x)
{
    __shared__ float S[8*257];
    int g = blockIdx.y, b = blockIdx.z;
    int pix0 = blockIdx.x * 256;
    int t = threadIdx.x;
    for (int i = t; i < 2048; i += 256) {
        int ch = i >> 8, px = i & 255;
        S[ch*257 + px] = x[((size_t)(b*128 + g*8 + ch))*HW + pix0 + px];
    }
    __syncthreads();
    for (int i = t; i < 2048; i += 256) {
        int px = i >> 3, ch = i & 7;
        g_xt[(((size_t)(b*16 + g))*HW + pix0 + px)*8 + ch] = __float2half(S[ch*257 + px]);
    }
}

// dcn weights -> fp16 hi/lo planes, [g][o][88], j=k*8+c
__global__ __launch_bounds__(256) void wdcn_k(const float* __restrict__ w)
{
    int i = blockIdx.x*256 + threadIdx.x;
    if (i >= 16*64*88) return;
    int j = i % 88;
    int o = (i / 88) % 64;
    int g = i / (88*64);
    float v = 0.f;
    if (j < 72) {
        int k = j >> 3, c = j & 7;
        v = w[(size_t)o*1152 + (g*8 + c)*9 + k];
    }
    __half h = __float2half(v);
    __half l = __float2half(v - __half2float(h));
    g_wth[i] = h;
    g_wtl[i] = l;
}

// out = bias (broadcast), float4 stores — dcn accumulates atomically on top
__global__ __launch_bounds__(256) void init_out_k(const float* __restrict__ bias,
                                                  float* __restrict__ out)
{
    int i = blockIdx.x*256 + threadIdx.x;      // over BB*64*HW/4
    if (i >= BB*64*HW/4) return;
    float bv = bias[(i >> 12) & 63];
    ((float4*)out)[i] = make_float4(bv, bv, bv, bv);
}

// ==================== mma.sync conv3x3 ====================
// CTA = (b, y, half-row): M=64 px, N=64 cout chunk (blockIdx.y), 256 thr (4Mx2N warps).
// RT: 3 halo rows x 66 px x 64ch hi/lo; B staged per-(cc,ky) as 3 kx tiles.
// 3-term bf16 split; mask-only cout chunks of conv4 (nc>=5) use 2 terms.
template<int CIN, int COUTP, int COUTR, int EPI>
__global__ __launch_bounds__(256) void convmma_k(
    const uint16_t* __restrict__ inh, const uint16_t* __restrict__ inl,
    const uint16_t* __restrict__ wh,  const uint16_t* __restrict__ wl,
    const float* __restrict__ bias,
    uint16_t* __restrict__ outh, uint16_t* __restrict__ outl,
    const float* __restrict__ flow1, const float* __restrict__ flow2)
{
    extern __shared__ char sm[];
    constexpr int CCH = (CIN + 63) / 64;
    constexpr int TAILK = (CIN % 64 != 0 && (CIN % 64) <= 16) ? 1 : 4;
    const int OFF_RTH = 0;           // 3*66*144 = 28512
    const int OFF_RTL = 28512;
    const int OFF_B   = 57024;       // 3 kx * (hi 9216 + lo 9216) = 55296

    uint32_t sbase = smem_u32(sm);
    int t = threadIdx.x, lane = t & 31, wid = t >> 5;
    int bx = blockIdx.x;
    int b = bx >> 8;
    int idx = bx & 255;
    int y = idx >> 1, x0 = (idx & 1) * 64;
    int nc = blockIdx.y;
    int warp_m = wid & 3, warp_n = wid >> 2;
    const bool full3 = (EPI == 0) || (nc < 5);   // mask-only chunks: 2-term

    float acc[4][4];
#pragma unroll
    for (int i = 0; i < 4; i++)
#pragma unroll
        for (int j2 = 0; j2 < 4; j2++) acc[i][j2] = 0.f;

    const uint32_t aH_row = sbase + OFF_RTH + (uint32_t)(warp_m*16 + (lane & 15))*144u;
    const uint32_t aL_row = sbase + OFF_RTL + (uint32_t)(warp_m*16 + (lane & 15))*144u;
    const int aseg = lane >> 4;
    const uint32_t brq = (uint32_t)(warp_n*32 + (lane & 7) + ((lane >> 4) & 1)*8)*144u;
    const int bseg = (lane >> 3) & 1;

    for (int cc = 0; cc < CCH; cc++) {
        __syncthreads();   // prev cc's ldsm done before RT overwrite
        {
            size_t imgoff = ((size_t)b*CCH + cc)*HW;
            for (int i = t; i < 3168; i += 256) {
                int f = i & 7;
                int rest = i >> 3;
                int p = rest % 66;
                int rest2 = rest / 66;
                int ry = rest2 % 3;
                int plane = rest2 / 3;
                int r = y + ry - 1, x = x0 + p - 1;
                uint32_t ok = ((unsigned)r < (unsigned)HH && (unsigned)x < (unsigned)WW) ? 16u : 0u;
                int rc = min(max(r, 0), HH-1), xc = min(max(x, 0), WW-1);
                const uint16_t* src = (plane ? inl : inh) + ((imgoff + (size_t)rc*WW + xc) << 6) + (f << 3);
                uint32_t dst = sbase + (plane ? OFF_RTL : OFF_RTH) + (ry*66 + p)*144 + f*16;
                CP_ASYNC16(dst, src, ok);
            }
            CP_COMMIT();
        }
        int nks = (cc == CCH - 1) ? TAILK : 4;
        for (int ky = 0; ky < 3; ky++) {
            int r = y + ky - 1;
            if ((unsigned)r >= (unsigned)HH) continue;   // uniform skip
            __syncthreads();   // prev ky's ldsm done before B overwrite
            {
                int j0 = cc*9 + ky*3;
                for (int i = t; i < 3456; i += 256) {
                    int c = i % 576;
                    int rest = i / 576;
                    int plane = rest & 1, kx = rest >> 1;
                    int o = c / 9, f = c % 9;
                    const uint16_t* src = (plane ? wl : wh)
                        + ((size_t)(j0 + kx)*COUTP + nc*64 + o)*72 + f*8;
                    uint32_t dst = sbase + OFF_B + (kx*2 + plane)*9216 + o*144 + f*16;
                    CP_ASYNC16(dst, src, 16u);
                }
                CP_COMMIT();
            }
            CP_WAIT0();
            __syncthreads();

            uint32_t rtH = aH_row + ky*66*144;
            uint32_t rtL = aL_row + ky*66*144;
#pragma unroll
            for (int kx = 0; kx < 3; kx++) {
                uint32_t aH0 = rtH + (uint32_t)kx*144u;
                uint32_t aL0 = rtL + (uint32_t)kx*144u;
                uint32_t bH  = sbase + OFF_B + kx*18432 + brq;
                uint32_t bL  = bH + 9216;
#pragma unroll 4
                for (int ks = 0; ks < nks; ks++) {
                    uint32_t ka = (uint32_t)(ks*16 + aseg*8)*2;
                    uint32_t kb = (uint32_t)(ks*16 + bseg*8)*2;
                    uint32_t a_h[4], a_l[4], b_h[2][4], b_l[2][4];
                    ldsm_x4(a_h, aH0 + ka);
                    if (full3) ldsm_x4(a_l, aL0 + ka);
                    ldsm_x4(b_h[0], bH + kb);
                    ldsm_x4(b_h[1], bH + 16*144 + kb);
                    ldsm_x4(b_l[0], bL + kb);
                    ldsm_x4(b_l[1], bL + 16*144 + kb);
#pragma unroll
                    for (int np = 0; np < 2; np++)
#pragma unroll
                        for (int sub = 0; sub < 2; sub++) {
                            int nt = np*2 + sub;
                            mma_bf16(acc[nt], a_h, &b_h[np][sub*2]);
                            mma_bf16(acc[nt], a_h, &b_l[np][sub*2]);
                            if (full3) mma_bf16(acc[nt], a_l, &b_h[np][sub*2]);
                        }
                }
            }
        }
    }

    int g = lane >> 2, tq = lane & 3;
    if (EPI == 0) {
        __syncthreads();    // all ldsm done before smem reuse
        uint32_t* OTH = (uint32_t*)sm;
        uint32_t* OTL = (uint32_t*)(sm + 9216);
#pragma unroll
        for (int nt = 0; nt < 4; nt++) {
            int cbase = warp_n*32 + nt*8 + tq*2;
            int c2 = cbase >> 1;
            float bv0 = bias[cbase], bv1 = bias[cbase + 1];
#pragma unroll
            for (int half = 0; half < 2; half++) {
                int px = warp_m*16 + g + half*8;
                float v0 = acc[nt][half*2]     + bv0;
                float v1 = acc[nt][half*2 + 1] + bv1;
                v0 = v0 >= 0.f ? v0 : 0.1f*v0;
                v1 = v1 >= 0.f ? v1 : 0.1f*v1;
                uint32_t u0 = pack_bf(v0), u1 = pack_bf(v1);
                OTH[px*36 + c2] = (u0 & 0xffffu) | (u1 << 16);
                OTL[px*36 + c2] = (u0 >> 16) | (u1 & 0xffff0000u);
            }
        }
        __syncthreads();
        for (int i = t; i < 512; i += 256) {
            int p = i >> 3, f = i & 7;
            size_t go = (((size_t)b*HW + y*WW + x0 + p) << 6) + (f << 3);
            *(float4*)(outh + go) = *(const float4*)((char*)OTH + p*144 + f*16);
            *(float4*)(outl + go) = *(const float4*)((char*)OTL + p*144 + f*16);
        }
    } else {
        float* dst = (float*)g_offm;
#pragma unroll
        for (int nt = 0; nt < 4; nt++)
#pragma unroll
            for (int rg = 0; rg < 4; rg++) {
                int px = warp_m*16 + g + ((rg >> 1) ? 8 : 0);
                int c  = nc*64 + warp_n*32 + nt*8 + tq*2 + (rg & 1);
                if (c >= COUTR) continue;
                int pix = y*WW + x0 + px;
                float v = acc[nt][rg] + bias[c];
                if (c < 288) {
                    int ch = c >> 1, comp = c & 1;
                    const float* fl = (c < 144) ? flow1 : flow2;
                    float add = fl[((size_t)b*2 + (1 - comp))*HW + pix];
                    dst[(((size_t)b*144 + ch)*HW + pix)*4 + comp] = 10.f*tanhf(v) + add;
                } else {
                    int ch = c - 288;
                    dst[(((size_t)b*144 + ch)*HW + pix)*4 + 2] = 1.f/(1.f + expf(-v));
                }
            }
    }
}

// ==================== dcn: two-phase fp16 gather + tensor-core GEMM + atomic reduce ====================
__global__ __launch_bounds__(256) void dcn4_k(float* __restrict__ out)
{
    __shared__ __align__(16) __half s_valT[64*88];
    __shared__ __align__(16) __half s_wh[64*88];
    __shared__ __align__(16) __half s_wl[64*88];
    int p0 = blockIdx.x << 6, b = blockIdx.y, q = blockIdx.z;
    int t = threadIdx.x, lane = t & 31, wid = t >> 5;
    int warp_m = wid & 3, warp_n = wid >> 2;

    float acc[4][4];
#pragma unroll
    for (int i = 0; i < 4; i++)
#pragma unroll
        for (int j2 = 0; j2 < 4; j2++) acc[i][j2] = 0.f;

    if (t < 128) {
        int p = t >> 1, f = t & 1;
        *(uint4*)(s_valT + p*88 + 72 + f*8) = make_uint4(0,0,0,0);
    }

    const float4* offm = g_offm + (size_t)b*144*HW;
    uint32_t sb_val = smem_u32(s_valT);
    uint32_t sb_wh  = smem_u32(s_wh);
    uint32_t sb_wl  = smem_u32(s_wl);

    const uint32_t aRow = (uint32_t)(warp_m*16 + (lane & 15))*176u + (uint32_t)((lane >> 4)*8)*2u;
    const uint32_t bRow = (uint32_t)(warp_n*32 + (lane & 7) + ((lane >> 4) & 1)*8)*176u
                        + (uint32_t)(((lane >> 3) & 1)*8)*2u;

    for (int gi = 0; gi < 4; gi++) {
        int g = q*4 + gi;
        __syncthreads();
        {
            const uint4* srch = (const uint4*)(g_wth + (size_t)g*64*88);
            const uint4* srcl = (const uint4*)(g_wtl + (size_t)g*64*88);
            uint4* dh = (uint4*)s_wh;
            uint4* dl = (uint4*)s_wl;
            for (int i = t; i < 704; i += 256) { dh[i] = srch[i]; dl[i] = srcl[i]; }
        }
        const __half* gb = g_xt + ((size_t)(b*16 + g))*HW*8;

        // ---- phase 1: compute weights + issue all gathers ----
        uint4  rr[3][4];
        float  wts[3][4];
#pragma unroll
        for (int rep = 0; rep < 3; rep++) {
            int task = t + (rep << 8);
            if (task < 576) {
                int k = task >> 6, p = task & 63;
                int pix = p0 + p, y = pix >> 7, x = pix & 127;
                int ch = g*9 + k;
                float4 om = offm[(size_t)ch*HW + pix];
                float m = om.z;
                float py = (float)(y + (k/3) - 1) + om.x;
                float px = (float)(x + (k%3) - 1) + om.y;
                float fy = floorf(py), fx = floorf(px);
                float wy = py - fy, wx = px - fx;
                int y0 = (int)fy, x0 = (int)fx, y1 = y0 + 1, x1 = x0 + 1;
                float vy0 = ((unsigned)y0 < HH) ? 1.f : 0.f;
                float vy1 = ((unsigned)y1 < HH) ? 1.f : 0.f;
                float vx0 = ((unsigned)x0 < WW) ? 1.f : 0.f;
                float vx1 = ((unsigned)x1 < WW) ? 1.f : 0.f;
                int y0c = min(max(y0,0),HH-1), y1c = min(max(y1,0),HH-1);
                int x0c = min(max(x0,0),WW-1), x1c = min(max(x1,0),WW-1);
                wts[rep][0] = (1.f-wy)*(1.f-wx)*m*vy0*vx0;
                wts[rep][1] = (1.f-wy)*wx      *m*vy0*vx1;
                wts[rep][2] = wy*(1.f-wx)      *m*vy1*vx0;
                wts[rep][3] = wy*wx            *m*vy1*vx1;
                rr[rep][0] = *(const uint4*)(gb + ((size_t)(y0c*WW + x0c) << 3));
                rr[rep][1] = *(const uint4*)(gb + ((size_t)(y0c*WW + x1c) << 3));
                rr[rep][2] = *(const uint4*)(gb + ((size_t)(y1c*WW + x0c) << 3));
                rr[rep][3] = *(const uint4*)(gb + ((size_t)(y1c*WW + x1c) << 3));
            }
        }
        // ---- phase 2: convert + store ----
#pragma unroll
        for (int rep = 0; rep < 3; rep++) {
            int task = t + (rep << 8);
            if (task < 576) {
                int k = task >> 6, p = task & 63;
                float w00 = wts[rep][0], w01 = wts[rep][1];
                float w10 = wts[rep][2], w11 = wts[rep][3];
                const __half2* h00 = (const __half2*)&rr[rep][0];
                const __half2* h01 = (const __half2*)&rr[rep][1];
                const __half2* h10 = (const __half2*)&rr[rep][2];
                const __half2* h11 = (const __half2*)&rr[rep][3];
                __half2 outp2[4];
#pragma unroll
                for (int i = 0; i < 4; i++) {
                    float2 f00 = __half22float2(h00[i]);
                    float2 f01 = __half22float2(h01[i]);
                    float2 f10 = __half22float2(h10[i]);
                    float2 f11 = __half22float2(h11[i]);
                    float v0 = w00*f00.x + w01*f01.x + w10*f10.x + w11*f11.x;
                    float v1 = w00*f00.y + w01*f01.y + w10*f10.y + w11*f11.y;
                    outp2[i] = __floats2half2_rn(v0, v1);
                }
                *(uint4*)(s_valT + p*88 + k*8) = *(const uint4*)outp2;
            }
        }
        __syncthreads();

#pragma unroll
        for (int ks = 0; ks < 5; ks++) {
            uint32_t kOff = (uint32_t)(ks*16)*2u;
            uint32_t a_h[4], a_l[4], bv[2][4];
            ldsm_x4(a_h, sb_wh + aRow + kOff);
            ldsm_x4(a_l, sb_wl + aRow + kOff);
            ldsm_x4(bv[0], sb_val + bRow + kOff);
            ldsm_x4(bv[1], sb_val + 16*176 + bRow + kOff);
#pragma unroll
            for (int np = 0; np < 2; np++)
#pragma unroll
                for (int sub = 0; sub < 2; sub++) {
                    int nt = np*2 + sub;
                    mma_f16(acc[nt], a_h, &bv[np][sub*2]);
                    mma_f16(acc[nt], a_l, &bv[np][sub*2]);
                }
        }
    }

    float* pout = out + (size_t)b*64*HW;
    int gg = lane >> 2, tq = lane & 3;
#pragma unroll
    for (int nt = 0; nt < 4; nt++)
#pragma unroll
        for (int rg = 0; rg < 4; rg++) {
            int o = warp_m*16 + gg + ((rg >> 1) ? 8 : 0);
            int p = warp_n*32 + nt*8 + tq*2 + (rg & 1);
            atomicAdd(&pout[(size_t)o*HW + p0 + p], acc[nt][rg]);
        }
}

// ==================== launch ====================
extern "C" void kernel_launch(void* const* d_in, const int* in_sizes, int n_in,
                              void* d_out, int out_size)
{
    const float* x   = (const float*)d_in[0];
    const float* exf = (const float*)d_in[1];
    const float* f1  = (const float*)d_in[2];
    const float* f2  = (const float*)d_in[3];
    const float* w1  = (const float*)d_in[4];
    const float* b1  = (const float*)d_in[5];
    const float* w2  = (const float*)d_in[6];
    const float* b2  = (const float*)d_in[7];
    const float* w3  = (const float*)d_in[8];
    const float* b3  = (const float*)d_in[9];
    const float* w4  = (const float*)d_in[10];
    const float* b4  = (const float*)d_in[11];
    const float* dw  = (const float*)d_in[12];
    const float* db  = (const float*)d_in[13];
    float* out = (float*)d_out;

    uint16_t *p_i0h, *p_i0l, *p_h1h, *p_h1l, *p_h2h, *p_h2l, *p_h3h, *p_h3l;
    uint16_t *p_w1h, *p_w1l, *p_w2h, *p_w2l, *p_w3h, *p_w3l, *p_w4h, *p_w4l;
    cudaGetSymbolAddress((void**)&p_i0h, g_in0h); cudaGetSymbolAddress((void**)&p_i0l, g_in0l);
    cudaGetSymbolAddress((void**)&p_h1h, g_h1h);  cudaGetSymbolAddress((void**)&p_h1l, g_h1l);
    cudaGetSymbolAddress((void**)&p_h2h, g_h2h);  cudaGetSymbolAddress((void**)&p_h2l, g_h2l);
    cudaGetSymbolAddress((void**)&p_h3h, g_h3h);  cudaGetSymbolAddress((void**)&p_h3l, g_h3l);
    cudaGetSymbolAddress((void**)&p_w1h, g_w1h);  cudaGetSymbolAddress((void**)&p_w1l, g_w1l);
    cudaGetSymbolAddress((void**)&p_w2h, g_w2h);  cudaGetSymbolAddress((void**)&p_w2l, g_w2l);
    cudaGetSymbolAddress((void**)&p_w3h, g_w3h);  cudaGetSymbolAddress((void**)&p_w3l, g_w3l);
    cudaGetSymbolAddress((void**)&p_w4h, g_w4h);  cudaGetSymbolAddress((void**)&p_w4l, g_w4l);

    const int SMTOT = 57024 + 55296;   // 112320
    cudaFuncSetAttribute(convmma_k<196,64,64,0>,  cudaFuncAttributeMaxDynamicSharedMemorySize, SMTOT);
    cudaFuncSetAttribute(convmma_k<64,64,64,0>,   cudaFuncAttributeMaxDynamicSharedMemorySize, SMTOT);
    cudaFuncSetAttribute(convmma_k<64,448,432,1>, cudaFuncAttributeMaxDynamicSharedMemorySize, SMTOT);

    pack_in0_k<<<dim3(HW/64, 4, BB), 256>>>(exf, f1, f2);
    transp_x_k<<<dim3(HW/256, 16, BB), 256>>>(x);
    wdcn_k<<<(16*64*88 + 255)/256, 256>>>(dw);
    init_out_k<<<(BB*64*HW/4 + 255)/256, 256>>>(db, out);
    wprep_k<<<(36*64*72  + 255)/256, 256>>>(w1, 196, 64, 64, 36, p_w1h, p_w1l);
    wprep_k<<<(9*64*72   + 255)/256, 256>>>(w2,  64, 64, 64,  9, p_w2h, p_w2l);
    wprep_k<<<(9*64*72   + 255)/256, 256>>>(w3,  64, 64, 64,  9, p_w3h, p_w3l);
    wprep_k<<<(9*448*72  + 255)/256, 256>>>(w4,  64, 432, 448, 9, p_w4h, p_w4l);

    convmma_k<196,64,64,0> <<<dim3(BB*256, 1), 256, SMTOT>>>(p_i0h, p_i0l, p_w1h, p_w1l, b1, p_h1h, p_h1l, nullptr, nullptr);
    convmma_k<64,64,64,0>  <<<dim3(BB*256, 1), 256, SMTOT>>>(p_h1h, p_h1l, p_w2h, p_w2l, b2, p_h2h, p_h2l, nullptr, nullptr);
    convmma_k<64,64,64,0>  <<<dim3(BB*256, 1), 256, SMTOT>>>(p_h2h, p_h2l, p_w3h, p_w3l, b3, p_h3h, p_h3l, nullptr, nullptr);
    convmma_k<64,448,432,1><<<dim3(BB*256, 7), 256, SMTOT>>>(p_h3h, p_h3l, p_w4h, p_w4l, b4, nullptr, nullptr, f1, f2);

    dcn4_k<<<dim3(256, BB, 4), 256>>>(out);
}

// round 16
// speedup vs baseline: 1.0471x; 1.0471x over previous
#include <cuda_runtime.h>
#include <cuda_bf16.h>
#include <cuda_fp16.h>
#include <math.h>
#include <stdint.h>

#define HH 128
#define WW 128
#define HW 16384
#define BB 2

// ==================== helpers ====================
__device__ __forceinline__ uint32_t smem_u32(const void* p) {
    uint32_t a;
    asm("{ .reg .u64 t; cvta.to.shared.u64 t, %1; cvt.u32.u64 %0, t; }" : "=r"(a) : "l"(p));
    return a;
}
__device__ __forceinline__ void ldsm_x4(uint32_t* r, uint32_t addr) {
    asm volatile("ldmatrix.sync.aligned.m8n8.x4.shared.b16 {%0,%1,%2,%3}, [%4];"
        : "=r"(r[0]), "=r"(r[1]), "=r"(r[2]), "=r"(r[3]) : "r"(addr));
}
__device__ __forceinline__ void mma_bf16(float* c, const uint32_t* a, const uint32_t* b) {
    asm volatile(
        "mma.sync.aligned.m16n8k16.row.col.f32.bf16.bf16.f32 "
        "{%0,%1,%2,%3}, {%4,%5,%6,%7}, {%8,%9}, {%0,%1,%2,%3};"
        : "+f"(c[0]), "+f"(c[1]), "+f"(c[2]), "+f"(c[3])
        : "r"(a[0]), "r"(a[1]), "r"(a[2]), "r"(a[3]), "r"(b[0]), "r"(b[1]));
}
__device__ __forceinline__ void mma_f16(float* c, const uint32_t* a, const uint32_t* b) {
    asm volatile(
        "mma.sync.aligned.m16n8k16.row.col.f32.f16.f16.f32 "
        "{%0,%1,%2,%3}, {%4,%5,%6,%7}, {%8,%9}, {%0,%1,%2,%3};"
        : "+f"(c[0]), "+f"(c[1]), "+f"(c[2]), "+f"(c[3])
        : "r"(a[0]), "r"(a[1]), "r"(a[2]), "r"(a[3]), "r"(b[0]), "r"(b[1]));
}
__device__ __forceinline__ uint32_t pack_bf(float v) {
    __nv_bfloat16 h = __float2bfloat16(v);
    float hf = __bfloat162float(h);
    __nv_bfloat16 l = __float2bfloat16(v - hf);
    return (uint32_t)__bfloat16_as_ushort(h) | ((uint32_t)__bfloat16_as_ushort(l) << 16);
}
#define CP_ASYNC16(dst, src, sz) \
    asm volatile("cp.async.cg.shared.global [%0], [%1], 16, %2;" \
        :: "r"(dst), "l"(src), "r"(sz))
#define CP_COMMIT()  asm volatile("cp.async.commit_group;" ::: "memory")
#define CP_WAIT0()   asm volatile("cp.async.wait_group 0;" ::: "memory")

// ==================== scratch globals ====================
__device__ __align__(16) uint16_t g_in0h[BB*4*HW*64], g_in0l[BB*4*HW*64];
__device__ __align__(16) uint16_t g_h1h [BB*HW*64],   g_h1l [BB*HW*64];
__device__ __align__(16) uint16_t g_h2h [BB*HW*64],   g_h2l [BB*HW*64];
__device__ __align__(16) uint16_t g_h3h [BB*HW*64],   g_h3l [BB*HW*64];
__device__ float4   g_offm[BB*144*HW];    // {oy, ox, mask, pad}
__device__ __align__(16) __half g_xt[BB*128*HW];  // x fp16 channels-last [b][g][pix][8]
// dcn weights fp16 2-plane, mma layout [g][o][88], j=k*8+c, 72..87 zero
__device__ __align__(16) __half g_wth[16*64*88], g_wtl[16*64*88];
// conv weight tiles: [j][CoutP rows][72 cols] bf16, zero-padded
__device__ __align__(16) uint16_t g_w1h[36*64*72],  g_w1l[36*64*72];
__device__ __align__(16) uint16_t g_w2h[9*64*72],   g_w2l[9*64*72];
__device__ __align__(16) uint16_t g_w3h[9*64*72],   g_w3l[9*64*72];
__device__ __align__(16) uint16_t g_w4h[9*448*72],  g_w4l[9*448*72];

// ==================== prep kernels ====================
__global__ __launch_bounds__(256) void pack_in0_k(
    const float* __restrict__ ef, const float* __restrict__ f1, const float* __restrict__ f2)
{
    __shared__ uint32_t S[64*65];
    int cc = blockIdx.y, b = blockIdx.z;
    int pix0 = blockIdx.x * 64;
    int t = threadIdx.x;
    for (int i = t; i < 4096; i += 256) {
        int ch = i >> 6, px = i & 63;
        int g = cc*64 + ch;
        float v = 0.f;
        if (g < 192)      v = ef[((size_t)b*192 + g)*HW + pix0 + px];
        else if (g < 194) v = f1[((size_t)b*2 + (g-192))*HW + pix0 + px];
        else if (g < 196) v = f2[((size_t)b*2 + (g-194))*HW + pix0 + px];
        S[ch*65 + px] = pack_bf(v);
    }
    __syncthreads();
    for (int i = t; i < 2048; i += 256) {
        int px = i >> 5, c2 = i & 31;
        uint32_t u0 = S[(c2*2)*65 + px];
        uint32_t u1 = S[(c2*2+1)*65 + px];
        size_t base = ((((size_t)b*4 + cc)*HW + pix0 + px) << 6) >> 1;
        ((uint32_t*)g_in0h)[base + c2] = (u0 & 0xffffu) | (u1 << 16);
        ((uint32_t*)g_in0l)[base + c2] = (u0 >> 16) | (u1 & 0xffff0000u);
    }
}

__global__ __launch_bounds__(256) void wprep_k(
    const float* __restrict__ w, int Cin, int CoutR, int CoutP, int J,
    uint16_t* __restrict__ dh, uint16_t* __restrict__ dl)
{
    int idx = blockIdx.x*256 + threadIdx.x;
    if (idx >= J*CoutP*72) return;
    int col = idx % 72;
    int o   = (idx / 72) % CoutP;
    int j   = idx / (72*CoutP);
    int cc = j / 9, kk = j % 9;
    int cin = cc*64 + col;
    float v = (col < 64 && cin < Cin && o < CoutR) ? w[((size_t)o*Cin + cin)*9 + kk] : 0.f;
    __nv_bfloat16 h = __float2bfloat16(v);
    float hf = __bfloat162float(h);
    __nv_bfloat16 l = __float2bfloat16(v - hf);
    dh[idx] = __bfloat16_as_ushort(h);
    dl[idx] = __bfloat16_as_ushort(l);
}

__global__ __launch_bounds__(256) void transp_x_k(const float* __restrict__ x)
{
    __shared__ float S[8*257];
    int g = blockIdx.y, b = blockIdx.z;
    int pix0 = blockIdx.x * 256;
    int t = threadIdx.x;
    for (int i = t; i < 2048; i += 256) {
        int ch = i >> 8, px = i & 255;
        S[ch*257 + px] = x[((size_t)(b*128 + g*8 + ch))*HW + pix0 + px];
    }
    __syncthreads();
    for (int i = t; i < 2048; i += 256) {
        int px = i >> 3, ch = i & 7;
        g_xt[(((size_t)(b*16 + g))*HW + pix0 + px)*8 + ch] = __float2half(S[ch*257 + px]);
    }
}

// dcn weights -> fp16 hi/lo planes, [g][o][88], j=k*8+c
__global__ __launch_bounds__(256) void wdcn_k(const float* __restrict__ w)
{
    int i = blockIdx.x*256 + threadIdx.x;
    if (i >= 16*64*88) return;
    int j = i % 88;
    int o = (i / 88) % 64;
    int g = i / (88*64);
    float v = 0.f;
    if (j < 72) {
        int k = j >> 3, c = j & 7;
        v = w[(size_t)o*1152 + (g*8 + c)*9 + k];
    }
    __half h = __float2half(v);
    __half l = __float2half(v - __half2float(h));
    g_wth[i] = h;
    g_wtl[i] = l;
}

// out = bias (broadcast), float4 stores — dcn accumulates atomically on top
__global__ __launch_bounds__(256) void init_out_k(const float* __restrict__ bias,
                                                  float* __restrict__ out)
{
    int i = blockIdx.x*256 + threadIdx.x;      // over BB*64*HW/4
    if (i >= BB*64*HW/4) return;
    float bv = bias[(i >> 12) & 63];
    ((float4*)out)[i] = make_float4(bv, bv, bv, bv);
}

// ==================== mma.sync conv3x3 ====================
// CTA = (b, y, half-row): M=64 px, N=64 cout chunk (blockIdx.y), 256 thr (4Mx2N warps).
// RT: 3 halo rows x 66 px x 64ch hi/lo; B staged per-(cc,ky) as 3 kx tiles.
// 3-term bf16 split; mask-only cout chunks of conv4 (nc>=5) use 2 terms.
template<int CIN, int COUTP, int COUTR, int EPI>
__global__ __launch_bounds__(256) void convmma_k(
    const uint16_t* __restrict__ inh, const uint16_t* __restrict__ inl,
    const uint16_t* __restrict__ wh,  const uint16_t* __restrict__ wl,
    const float* __restrict__ bias,
    uint16_t* __restrict__ outh, uint16_t* __restrict__ outl,
    const float* __restrict__ flow1, const float* __restrict__ flow2)
{
    extern __shared__ char sm[];
    constexpr int CCH = (CIN + 63) / 64;
    constexpr int TAILK = (CIN % 64 != 0 && (CIN % 64) <= 16) ? 1 : 4;
    const int OFF_RTH = 0;           // 3*66*144 = 28512
    const int OFF_RTL = 28512;
    const int OFF_B   = 57024;       // 3 kx * (hi 9216 + lo 9216) = 55296

    uint32_t sbase = smem_u32(sm);
    int t = threadIdx.x, lane = t & 31, wid = t >> 5;
    int bx = blockIdx.x;
    int b = bx >> 8;
    int idx = bx & 255;
    int y = idx >> 1, x0 = (idx & 1) * 64;
    int nc = blockIdx.y;
    int warp_m = wid & 3, warp_n = wid >> 2;
    const bool full3 = (EPI == 0) || (nc < 5);   // mask-only chunks: 2-term

    float acc[4][4];
#pragma unroll
    for (int i = 0; i < 4; i++)
#pragma unroll
        for (int j2 = 0; j2 < 4; j2++) acc[i][j2] = 0.f;

    const uint32_t aH_row = sbase + OFF_RTH + (uint32_t)(warp_m*16 + (lane & 15))*144u;
    const uint32_t aL_row = sbase + OFF_RTL + (uint32_t)(warp_m*16 + (lane & 15))*144u;
    const int aseg = lane >> 4;
    const uint32_t brq = (uint32_t)(warp_n*32 + (lane & 7) + ((lane >> 4) & 1)*8)*144u;
    const int bseg = (lane >> 3) & 1;

    for (int cc = 0; cc < CCH; cc++) {
        __syncthreads();   // prev cc's ldsm done before RT overwrite
        {
            size_t imgoff = ((size_t)b*CCH + cc)*HW;
            for (int i = t; i < 3168; i += 256) {
                int f = i & 7;
                int rest = i >> 3;
                int p = rest % 66;
                int rest2 = rest / 66;
                int ry = rest2 % 3;
                int plane = rest2 / 3;
                int r = y + ry - 1, x = x0 + p - 1;
                uint32_t ok = ((unsigned)r < (unsigned)HH && (unsigned)x < (unsigned)WW) ? 16u : 0u;
                int rc = min(max(r, 0), HH-1), xc = min(max(x, 0), WW-1);
                const uint16_t* src = (plane ? inl : inh) + ((imgoff + (size_t)rc*WW + xc) << 6) + (f << 3);
                uint32_t dst = sbase + (plane ? OFF_RTL : OFF_RTH) + (ry*66 + p)*144 + f*16;
                CP_ASYNC16(dst, src, ok);
            }
            CP_COMMIT();
        }
        int nks = (cc == CCH - 1) ? TAILK : 4;
        for (int ky = 0; ky < 3; ky++) {
            int r = y + ky - 1;
            if ((unsigned)r >= (unsigned)HH) continue;   // uniform skip
            __syncthreads();   // prev ky's ldsm done before B overwrite
            {
                int j0 = cc*9 + ky*3;
                for (int i = t; i < 3456; i += 256) {
                    int c = i % 576;
                    int rest = i / 576;
                    int plane = rest & 1, kx = rest >> 1;
                    int o = c / 9, f = c % 9;
                    const uint16_t* src = (plane ? wl : wh)
                        + ((size_t)(j0 + kx)*COUTP + nc*64 + o)*72 + f*8;
                    uint32_t dst = sbase + OFF_B + (kx*2 + plane)*9216 + o*144 + f*16;
                    CP_ASYNC16(dst, src, 16u);
                }
                CP_COMMIT();
            }
            CP_WAIT0();
            __syncthreads();

            uint32_t rtH = aH_row + ky*66*144;
            uint32_t rtL = aL_row + ky*66*144;
#pragma unroll
            for (int kx = 0; kx < 3; kx++) {
                uint32_t aH0 = rtH + (uint32_t)kx*144u;
                uint32_t aL0 = rtL + (uint32_t)kx*144u;
                uint32_t bH  = sbase + OFF_B + kx*18432 + brq;
                uint32_t bL  = bH + 9216;
#pragma unroll 4
                for (int ks = 0; ks < nks; ks++) {
                    uint32_t ka = (uint32_t)(ks*16 + aseg*8)*2;
                    uint32_t kb = (uint32_t)(ks*16 + bseg*8)*2;
                    uint32_t a_h[4], a_l[4], b_h[2][4], b_l[2][4];
                    ldsm_x4(a_h, aH0 + ka);
                    if (full3) ldsm_x4(a_l, aL0 + ka);
                    ldsm_x4(b_h[0], bH + kb);
                    ldsm_x4(b_h[1], bH + 16*144 + kb);
                    ldsm_x4(b_l[0], bL + kb);
                    ldsm_x4(b_l[1], bL + 16*144 + kb);
#pragma unroll
                    for (int np = 0; np < 2; np++)
#pragma unroll
                        for (int sub = 0; sub < 2; sub++) {
                            int nt = np*2 + sub;
                            mma_bf16(acc[nt], a_h, &b_h[np][sub*2]);
                            mma_bf16(acc[nt], a_h, &b_l[np][sub*2]);
                            if (full3) mma_bf16(acc[nt], a_l, &b_h[np][sub*2]);
                        }
                }
            }
        }
    }

    int g = lane >> 2, tq = lane & 3;
    if (EPI == 0) {
        __syncthreads();    // all ldsm done before smem reuse
        uint32_t* OTH = (uint32_t*)sm;
        uint32_t* OTL = (uint32_t*)(sm + 9216);
#pragma unroll
        for (int nt = 0; nt < 4; nt++) {
            int cbase = warp_n*32 + nt*8 + tq*2;
            int c2 = cbase >> 1;
            float bv0 = bias[cbase], bv1 = bias[cbase + 1];
#pragma unroll
            for (int half = 0; half < 2; half++) {
                int px = warp_m*16 + g + half*8;
                float v0 = acc[nt][half*2]     + bv0;
                float v1 = acc[nt][half*2 + 1] + bv1;
                v0 = v0 >= 0.f ? v0 : 0.1f*v0;
                v1 = v1 >= 0.f ? v1 : 0.1f*v1;
                uint32_t u0 = pack_bf(v0), u1 = pack_bf(v1);
                OTH[px*36 + c2] = (u0 & 0xffffu) | (u1 << 16);
                OTL[px*36 + c2] = (u0 >> 16) | (u1 & 0xffff0000u);
            }
        }
        __syncthreads();
        for (int i = t; i < 512; i += 256) {
            int p = i >> 3, f = i & 7;
            size_t go = (((size_t)b*HW + y*WW + x0 + p) << 6) + (f << 3);
            *(float4*)(outh + go) = *(const float4*)((char*)OTH + p*144 + f*16);
            *(float4*)(outl + go) = *(const float4*)((char*)OTL + p*144 + f*16);
        }
    } else {
        float* dst = (float*)g_offm;
#pragma unroll
        for (int nt = 0; nt < 4; nt++)
#pragma unroll
            for (int rg = 0; rg < 4; rg++) {
                int px = warp_m*16 + g + ((rg >> 1) ? 8 : 0);
                int c  = nc*64 + warp_n*32 + nt*8 + tq*2 + (rg & 1);
                if (c >= COUTR) continue;
                int pix = y*WW + x0 + px;
                float v = acc[nt][rg] + bias[c];
                if (c < 288) {
                    int ch = c >> 1, comp = c & 1;
                    const float* fl = (c < 144) ? flow1 : flow2;
                    float add = fl[((size_t)b*2 + (1 - comp))*HW + pix];
                    dst[(((size_t)b*144 + ch)*HW + pix)*4 + comp] = 10.f*tanhf(v) + add;
                } else {
                    int ch = c - 288;
                    dst[(((size_t)b*144 + ch)*HW + pix)*4 + 2] = 1.f/(1.f + expf(-v));
                }
            }
    }
}

// ==================== dcn: fp16 gather + tensor-core GEMM + atomic reduce (R14) ====================
__global__ __launch_bounds__(256) void dcn4_k(float* __restrict__ out)
{
    __shared__ __align__(16) __half s_valT[64*88];
    __shared__ __align__(16) __half s_wh[64*88];
    __shared__ __align__(16) __half s_wl[64*88];
    int p0 = blockIdx.x << 6, b = blockIdx.y, q = blockIdx.z;
    int t = threadIdx.x, lane = t & 31, wid = t >> 5;
    int warp_m = wid & 3, warp_n = wid >> 2;

    float acc[4][4];
#pragma unroll
    for (int i = 0; i < 4; i++)
#pragma unroll
        for (int j2 = 0; j2 < 4; j2++) acc[i][j2] = 0.f;

    if (t < 128) {
        int p = t >> 1, f = t & 1;
        *(uint4*)(s_valT + p*88 + 72 + f*8) = make_uint4(0,0,0,0);
    }

    const float4* offm = g_offm + (size_t)b*144*HW;
    uint32_t sb_val = smem_u32(s_valT);
    uint32_t sb_wh  = smem_u32(s_wh);
    uint32_t sb_wl  = smem_u32(s_wl);

    const uint32_t aRow = (uint32_t)(warp_m*16 + (lane & 15))*176u + (uint32_t)((lane >> 4)*8)*2u;
    const uint32_t bRow = (uint32_t)(warp_n*32 + (lane & 7) + ((lane >> 4) & 1)*8)*176u
                        + (uint32_t)(((lane >> 3) & 1)*8)*2u;

    for (int gi = 0; gi < 4; gi++) {
        int g = q*4 + gi;
        __syncthreads();
        {
            const uint4* srch = (const uint4*)(g_wth + (size_t)g*64*88);
            const uint4* srcl = (const uint4*)(g_wtl + (size_t)g*64*88);
            uint4* dh = (uint4*)s_wh;
            uint4* dl = (uint4*)s_wl;
            for (int i = t; i < 704; i += 256) { dh[i] = srch[i]; dl[i] = srcl[i]; }
        }
        const __half* gb = g_xt + ((size_t)(b*16 + g))*HW*8;
#pragma unroll
        for (int rep = 0; rep < 3; rep++) {
            int task = t + (rep << 8);
            if (task < 576) {
                int k = task >> 6, p = task & 63;
                int pix = p0 + p, y = pix >> 7, x = pix & 127;
                int ch = g*9 + k;
                float4 om = offm[(size_t)ch*HW + pix];
                float m = om.z;
                float py = (float)(y + (k/3) - 1) + om.x;
                float px = (float)(x + (k%3) - 1) + om.y;
                float fy = floorf(py), fx = floorf(px);
                float wy = py - fy, wx = px - fx;
                int y0 = (int)fy, x0 = (int)fx, y1 = y0 + 1, x1 = x0 + 1;
                float vy0 = ((unsigned)y0 < HH) ? 1.f : 0.f;
                float vy1 = ((unsigned)y1 < HH) ? 1.f : 0.f;
                float vx0 = ((unsigned)x0 < WW) ? 1.f : 0.f;
                float vx1 = ((unsigned)x1 < WW) ? 1.f : 0.f;
                int y0c = min(max(y0,0),HH-1), y1c = min(max(y1,0),HH-1);
                int x0c = min(max(x0,0),WW-1), x1c = min(max(x1,0),WW-1);
                float w00 = (1.f-wy)*(1.f-wx)*m*vy0*vx0;
                float w01 = (1.f-wy)*wx      *m*vy0*vx1;
                float w10 = wy*(1.f-wx)      *m*vy1*vx0;
                float w11 = wy*wx            *m*vy1*vx1;
                uint4 r00 = *(const uint4*)(gb + ((size_t)(y0c*WW + x0c) << 3));
                uint4 r01 = *(const uint4*)(gb + ((size_t)(y0c*WW + x1c) << 3));
                uint4 r10 = *(const uint4*)(gb + ((size_t)(y1c*WW + x0c) << 3));
                uint4 r11 = *(const uint4*)(gb + ((size_t)(y1c*WW + x1c) << 3));
                const __half2* h00 = (const __half2*)&r00;
                const __half2* h01 = (const __half2*)&r01;
                const __half2* h10 = (const __half2*)&r10;
                const __half2* h11 = (const __half2*)&r11;
                __half2 outp2[4];
#pragma unroll
                for (int i = 0; i < 4; i++) {
                    float2 f00 = __half22float2(h00[i]);
                    float2 f01 = __half22float2(h01[i]);
                    float2 f10 = __half22float2(h10[i]);
                    float2 f11 = __half22float2(h11[i]);
                    float v0 = w00*f00.x + w01*f01.x + w10*f10.x + w11*f11.x;
                    float v1 = w00*f00.y + w01*f01.y + w10*f10.y + w11*f11.y;
                    outp2[i] = __floats2half2_rn(v0, v1);
                }
                *(uint4*)(s_valT + p*88 + k*8) = *(const uint4*)outp2;
            }
        }
        __syncthreads();

#pragma unroll
        for (int ks = 0; ks < 5; ks++) {
            uint32_t kOff = (uint32_t)(ks*16)*2u;
            uint32_t a_h[4], a_l[4], bv[2][4];
            ldsm_x4(a_h, sb_wh + aRow + kOff);
            ldsm_x4(a_l, sb_wl + aRow + kOff);
            ldsm_x4(bv[0], sb_val + bRow + kOff);
            ldsm_x4(bv[1], sb_val + 16*176 + bRow + kOff);
#pragma unroll
            for (int np = 0; np < 2; np++)
#pragma unroll
                for (int sub = 0; sub < 2; sub++) {
                    int nt = np*2 + sub;
                    mma_f16(acc[nt], a_h, &bv[np][sub*2]);
                    mma_f16(acc[nt], a_l, &bv[np][sub*2]);
                }
        }
    }

    float* pout = out + (size_t)b*64*HW;
    int gg = lane >> 2, tq = lane & 3;
#pragma unroll
    for (int nt = 0; nt < 4; nt++)
#pragma unroll
        for (int rg = 0; rg < 4; rg++) {
            int o = warp_m*16 + gg + ((rg >> 1) ? 8 : 0);
            int p = warp_n*32 + nt*8 + tq*2 + (rg & 1);
            atomicAdd(&pout[(size_t)o*HW + p0 + p], acc[nt][rg]);
        }
}

// ==================== launch ====================
extern "C" void kernel_launch(void* const* d_in, const int* in_sizes, int n_in,
                              void* d_out, int out_size)
{
    const float* x   = (const float*)d_in[0];
    const float* exf = (const float*)d_in[1];
    const float* f1  = (const float*)d_in[2];
    const float* f2  = (const float*)d_in[3];
    const float* w1  = (const float*)d_in[4];
    const float* b1  = (const float*)d_in[5];
    const float* w2  = (const float*)d_in[6];
    const float* b2  = (const float*)d_in[7];
    const float* w3  = (const float*)d_in[8];
    const float* b3  = (const float*)d_in[9];
    const float* w4  = (const float*)d_in[10];
    const float* b4  = (const float*)d_in[11];
    const float* dw  = (const float*)d_in[12];
    const float* db  = (const float*)d_in[13];
    float* out = (float*)d_out;

    uint16_t *p_i0h, *p_i0l, *p_h1h, *p_h1l, *p_h2h, *p_h2l, *p_h3h, *p_h3l;
    uint16_t *p_w1h, *p_w1l, *p_w2h, *p_w2l, *p_w3h, *p_w3l, *p_w4h, *p_w4l;
    cudaGetSymbolAddress((void**)&p_i0h, g_in0h); cudaGetSymbolAddress((void**)&p_i0l, g_in0l);
    cudaGetSymbolAddress((void**)&p_h1h, g_h1h);  cudaGetSymbolAddress((void**)&p_h1l, g_h1l);
    cudaGetSymbolAddress((void**)&p_h2h, g_h2h);  cudaGetSymbolAddress((void**)&p_h2l, g_h2l);
    cudaGetSymbolAddress((void**)&p_h3h, g_h3h);  cudaGetSymbolAddress((void**)&p_h3l, g_h3l);
    cudaGetSymbolAddress((void**)&p_w1h, g_w1h);  cudaGetSymbolAddress((void**)&p_w1l, g_w1l);
    cudaGetSymbolAddress((void**)&p_w2h, g_w2h);  cudaGetSymbolAddress((void**)&p_w2l, g_w2l);
    cudaGetSymbolAddress((void**)&p_w3h, g_w3h);  cudaGetSymbolAddress((void**)&p_w3l, g_w3l);
    cudaGetSymbolAddress((void**)&p_w4h, g_w4h);  cudaGetSymbolAddress((void**)&p_w4l, g_w4l);

    const int SMTOT = 57024 + 55296;   // 112320
    cudaFuncSetAttribute(convmma_k<196,64,64,0>,  cudaFuncAttributeMaxDynamicSharedMemorySize, SMTOT);
    cudaFuncSetAttribute(convmma_k<64,64,64,0>,   cudaFuncAttributeMaxDynamicSharedMemorySize, SMTOT);
    cudaFuncSetAttribute(convmma_k<64,448,432,1>, cudaFuncAttributeMaxDynamicSharedMemorySize, SMTOT);

    pack_in0_k<<<dim3(HW/64, 4, BB), 256>>>(exf, f1, f2);
    transp_x_k<<<dim3(HW/256, 16, BB), 256>>>(x);
    wdcn_k<<<(16*64*88 + 255)/256, 256>>>(dw);
    init_out_k<<<(BB*64*HW/4 + 255)/256, 256>>>(db, out);
    wprep_k<<<(36*64*72  + 255)/256, 256>>>(w1, 196, 64, 64, 36, p_w1h, p_w1l);
    wprep_k<<<(9*64*72   + 255)/256, 256>>>(w2,  64, 64, 64,  9, p_w2h, p_w2l);
    wprep_k<<<(9*64*72   + 255)/256, 256>>>(w3,  64, 64, 64,  9, p_w3h, p_w3l);
    wprep_k<<<(9*448*72  + 255)/256, 256>>>(w4,  64, 432, 448, 9, p_w4h, p_w4l);

    convmma_k<196,64,64,0> <<<dim3(BB*256, 1), 256, SMTOT>>>(p_i0h, p_i0l, p_w1h, p_w1l, b1, p_h1h, p_h1l, nullptr, nullptr);
    convmma_k<64,64,64,0>  <<<dim3(BB*256, 1), 256, SMTOT>>>(p_h1h, p_h1l, p_w2h, p_w2l, b2, p_h2h, p_h2l, nullptr, nullptr);
    convmma_k<64,64,64,0>  <<<dim3(BB*256, 1), 256, SMTOT>>>(p_h2h, p_h2l, p_w3h, p_w3l, b3, p_h3h, p_h3l, nullptr, nullptr);
    convmma_k<64,448,432,1><<<dim3(BB*256, 7), 256, SMTOT>>>(p_h3h, p_h3l, p_w4h, p_w4l, b4, nullptr, nullptr, f1, f2);

    dcn4_k<<<dim3(256, BB, 4), 256>>>(out);
}

// round 17
// speedup vs baseline: 1.0578x; 1.0102x over previous
#include <cuda_runtime.h>
#include <cuda_bf16.h>
#include <cuda_fp16.h>
#include <math.h>
#include <stdint.h>

#define HH 128
#define WW 128
#define HW 16384
#define BB 2

// ==================== helpers ====================
__device__ __forceinline__ uint32_t smem_u32(const void* p) {
    uint32_t a;
    asm("{ .reg .u64 t; cvta.to.shared.u64 t, %1; cvt.u32.u64 %0, t; }" : "=r"(a) : "l"(p));
    return a;
}
__device__ __forceinline__ void ldsm_x4(uint32_t* r, uint32_t addr) {
    asm volatile("ldmatrix.sync.aligned.m8n8.x4.shared.b16 {%0,%1,%2,%3}, [%4];"
        : "=r"(r[0]), "=r"(r[1]), "=r"(r[2]), "=r"(r[3]) : "r"(addr));
}
__device__ __forceinline__ void mma_bf16(float* c, const uint32_t* a, const uint32_t* b) {
    asm volatile(
        "mma.sync.aligned.m16n8k16.row.col.f32.bf16.bf16.f32 "
        "{%0,%1,%2,%3}, {%4,%5,%6,%7}, {%8,%9}, {%0,%1,%2,%3};"
        : "+f"(c[0]), "+f"(c[1]), "+f"(c[2]), "+f"(c[3])
        : "r"(a[0]), "r"(a[1]), "r"(a[2]), "r"(a[3]), "r"(b[0]), "r"(b[1]));
}
__device__ __forceinline__ void mma_f16(float* c, const uint32_t* a, const uint32_t* b) {
    asm volatile(
        "mma.sync.aligned.m16n8k16.row.col.f32.f16.f16.f32 "
        "{%0,%1,%2,%3}, {%4,%5,%6,%7}, {%8,%9}, {%0,%1,%2,%3};"
        : "+f"(c[0]), "+f"(c[1]), "+f"(c[2]), "+f"(c[3])
        : "r"(a[0]), "r"(a[1]), "r"(a[2]), "r"(a[3]), "r"(b[0]), "r"(b[1]));
}
__device__ __forceinline__ uint32_t pack_bf(float v) {
    __nv_bfloat16 h = __float2bfloat16(v);
    float hf = __bfloat162float(h);
    __nv_bfloat16 l = __float2bfloat16(v - hf);
    return (uint32_t)__bfloat16_as_ushort(h) | ((uint32_t)__bfloat16_as_ushort(l) << 16);
}
#define CP_ASYNC16(dst, src, sz) \
    asm volatile("cp.async.cg.shared.global [%0], [%1], 16, %2;" \
        :: "r"(dst), "l"(src), "r"(sz))
#define CP_COMMIT()  asm volatile("cp.async.commit_group;" ::: "memory")
#define CP_WAIT0()   asm volatile("cp.async.wait_group 0;" ::: "memory")

// ==================== scratch globals ====================
__device__ __align__(16) uint16_t g_in0h[BB*4*HW*64], g_in0l[BB*4*HW*64];
__device__ __align__(16) uint16_t g_h1h [BB*HW*64],   g_h1l [BB*HW*64];
__device__ __align__(16) uint16_t g_h2h [BB*HW*64],   g_h2l [BB*HW*64];
__device__ __align__(16) uint16_t g_h3h [BB*HW*64],   g_h3l [BB*HW*64];
__device__ float4   g_offm[BB*144*HW];    // {oy, ox, mask, pad}
__device__ __align__(16) __half g_xt[BB*128*HW];  // x fp16 channels-last [b][g][pix][8]
// dcn weights fp16 2-plane, mma layout [g][o][88], j=k*8+c, 72..87 zero
__device__ __align__(16) __half g_wth[16*64*88], g_wtl[16*64*88];
// conv weight tiles: [j][CoutP rows][72 cols] bf16, zero-padded
__device__ __align__(16) uint16_t g_w1h[36*64*72],  g_w1l[36*64*72];
__device__ __align__(16) uint16_t g_w2h[9*64*72],   g_w2l[9*64*72];
__device__ __align__(16) uint16_t g_w3h[9*64*72],   g_w3l[9*64*72];
__device__ __align__(16) uint16_t g_w4h[9*448*72],  g_w4l[9*448*72];

// ==================== prep kernels ====================
__global__ __launch_bounds__(256) void pack_in0_k(
    const float* __restrict__ ef, const float* __restrict__ f1, const float* __restrict__ f2)
{
    __shared__ uint32_t S[64*65];
    int cc = blockIdx.y, b = blockIdx.z;
    int pix0 = blockIdx.x * 64;
    int t = threadIdx.x;
    for (int i = t; i < 4096; i += 256) {
        int ch = i >> 6, px = i & 63;
        int g = cc*64 + ch;
        float v = 0.f;
        if (g < 192)      v = ef[((size_t)b*192 + g)*HW + pix0 + px];
        else if (g < 194) v = f1[((size_t)b*2 + (g-192))*HW + pix0 + px];
        else if (g < 196) v = f2[((size_t)b*2 + (g-194))*HW + pix0 + px];
        S[ch*65 + px] = pack_bf(v);
    }
    __syncthreads();
    for (int i = t; i < 2048; i += 256) {
        int px = i >> 5, c2 = i & 31;
        uint32_t u0 = S[(c2*2)*65 + px];
        uint32_t u1 = S[(c2*2+1)*65 + px];
        size_t base = ((((size_t)b*4 + cc)*HW + pix0 + px) << 6) >> 1;
        ((uint32_t*)g_in0h)[base + c2] = (u0 & 0xffffu) | (u1 << 16);
        ((uint32_t*)g_in0l)[base + c2] = (u0 >> 16) | (u1 & 0xffff0000u);
    }
}

__global__ __launch_bounds__(256) void wprep_k(
    const float* __restrict__ w, int Cin, int CoutR, int CoutP, int J,
    uint16_t* __restrict__ dh, uint16_t* __restrict__ dl)
{
    int idx = blockIdx.x*256 + threadIdx.x;
    if (idx >= J*CoutP*72) return;
    int col = idx % 72;
    int o   = (idx / 72) % CoutP;
    int j   = idx / (72*CoutP);
    int cc = j / 9, kk = j % 9;
    int cin = cc*64 + col;
    float v = (col < 64 && cin < Cin && o < CoutR) ? w[((size_t)o*Cin + cin)*9 + kk] : 0.f;
    __nv_bfloat16 h = __float2bfloat16(v);
    float hf = __bfloat162float(h);
    __nv_bfloat16 l = __float2bfloat16(v - hf);
    dh[idx] = __bfloat16_as_ushort(h);
    dl[idx] = __bfloat16_as_ushort(l);
}

__global__ __launch_bounds__(256) void transp_x_k(const float* __restrict__ x)
{
    __shared__ float S[8*257];
    int g = blockIdx.y, b = blockIdx.z;
    int pix0 = blockIdx.x * 256;
    int t = threadIdx.x;
    for (int i = t; i < 2048; i += 256) {
        int ch = i >> 8, px = i & 255;
        S[ch*257 + px] = x[((size_t)(b*128 + g*8 + ch))*HW + pix0 + px];
    }
    __syncthreads();
    for (int i = t; i < 2048; i += 256) {
        int px = i >> 3, ch = i & 7;
        g_xt[(((size_t)(b*16 + g))*HW + pix0 + px)*8 + ch] = __float2half(S[ch*257 + px]);
    }
}

// dcn weights -> fp16 hi/lo planes, [g][o][88], j=k*8+c
__global__ __launch_bounds__(256) void wdcn_k(const float* __restrict__ w)
{
    int i = blockIdx.x*256 + threadIdx.x;
    if (i >= 16*64*88) return;
    int j = i % 88;
    int o = (i / 88) % 64;
    int g = i / (88*64);
    float v = 0.f;
    if (j < 72) {
        int k = j >> 3, c = j & 7;
        v = w[(size_t)o*1152 + (g*8 + c)*9 + k];
    }
    __half h = __float2half(v);
    __half l = __float2half(v - __half2float(h));
    g_wth[i] = h;
    g_wtl[i] = l;
}

// out = bias (broadcast), float4 stores — dcn accumulates atomically on top
__global__ __launch_bounds__(256) void init_out_k(const float* __restrict__ bias,
                                                  float* __restrict__ out)
{
    int i = blockIdx.x*256 + threadIdx.x;      // over BB*64*HW/4
    if (i >= BB*64*HW/4) return;
    float bv = bias[(i >> 12) & 63];
    ((float4*)out)[i] = make_float4(bv, bv, bv, bv);
}

// ==================== mma.sync conv3x3 (unchanged R16) ====================
template<int CIN, int COUTP, int COUTR, int EPI>
__global__ __launch_bounds__(256) void convmma_k(
    const uint16_t* __restrict__ inh, const uint16_t* __restrict__ inl,
    const uint16_t* __restrict__ wh,  const uint16_t* __restrict__ wl,
    const float* __restrict__ bias,
    uint16_t* __restrict__ outh, uint16_t* __restrict__ outl,
    const float* __restrict__ flow1, const float* __restrict__ flow2)
{
    extern __shared__ char sm[];
    constexpr int CCH = (CIN + 63) / 64;
    constexpr int TAILK = (CIN % 64 != 0 && (CIN % 64) <= 16) ? 1 : 4;
    const int OFF_RTH = 0;           // 3*66*144 = 28512
    const int OFF_RTL = 28512;
    const int OFF_B   = 57024;       // 3 kx * (hi 9216 + lo 9216) = 55296

    uint32_t sbase = smem_u32(sm);
    int t = threadIdx.x, lane = t & 31, wid = t >> 5;
    int bx = blockIdx.x;
    int b = bx >> 8;
    int idx = bx & 255;
    int y = idx >> 1, x0 = (idx & 1) * 64;
    int nc = blockIdx.y;
    int warp_m = wid & 3, warp_n = wid >> 2;
    const bool full3 = (EPI == 0) || (nc < 5);   // mask-only chunks: 2-term

    float acc[4][4];
#pragma unroll
    for (int i = 0; i < 4; i++)
#pragma unroll
        for (int j2 = 0; j2 < 4; j2++) acc[i][j2] = 0.f;

    const uint32_t aH_row = sbase + OFF_RTH + (uint32_t)(warp_m*16 + (lane & 15))*144u;
    const uint32_t aL_row = sbase + OFF_RTL + (uint32_t)(warp_m*16 + (lane & 15))*144u;
    const int aseg = lane >> 4;
    const uint32_t brq = (uint32_t)(warp_n*32 + (lane & 7) + ((lane >> 4) & 1)*8)*144u;
    const int bseg = (lane >> 3) & 1;

    for (int cc = 0; cc < CCH; cc++) {
        __syncthreads();   // prev cc's ldsm done before RT overwrite
        {
            size_t imgoff = ((size_t)b*CCH + cc)*HW;
            for (int i = t; i < 3168; i += 256) {
                int f = i & 7;
                int rest = i >> 3;
                int p = rest % 66;
                int rest2 = rest / 66;
                int ry = rest2 % 3;
                int plane = rest2 / 3;
                int r = y + ry - 1, x = x0 + p - 1;
                uint32_t ok = ((unsigned)r < (unsigned)HH && (unsigned)x < (unsigned)WW) ? 16u : 0u;
                int rc = min(max(r, 0), HH-1), xc = min(max(x, 0), WW-1);
                const uint16_t* src = (plane ? inl : inh) + ((imgoff + (size_t)rc*WW + xc) << 6) + (f << 3);
                uint32_t dst = sbase + (plane ? OFF_RTL : OFF_RTH) + (ry*66 + p)*144 + f*16;
                CP_ASYNC16(dst, src, ok);
            }
            CP_COMMIT();
        }
        int nks = (cc == CCH - 1) ? TAILK : 4;
        for (int ky = 0; ky < 3; ky++) {
            int r = y + ky - 1;
            if ((unsigned)r >= (unsigned)HH) continue;   // uniform skip
            __syncthreads();   // prev ky's ldsm done before B overwrite
            {
                int j0 = cc*9 + ky*3;
                for (int i = t; i < 3456; i += 256) {
                    int c = i % 576;
                    int rest = i / 576;
                    int plane = rest & 1, kx = rest >> 1;
                    int o = c / 9, f = c % 9;
                    const uint16_t* src = (plane ? wl : wh)
                        + ((size_t)(j0 + kx)*COUTP + nc*64 + o)*72 + f*8;
                    uint32_t dst = sbase + OFF_B + (kx*2 + plane)*9216 + o*144 + f*16;
                    CP_ASYNC16(dst, src, 16u);
                }
                CP_COMMIT();
            }
            CP_WAIT0();
            __syncthreads();

            uint32_t rtH = aH_row + ky*66*144;
            uint32_t rtL = aL_row + ky*66*144;
#pragma unroll
            for (int kx = 0; kx < 3; kx++) {
                uint32_t aH0 = rtH + (uint32_t)kx*144u;
                uint32_t aL0 = rtL + (uint32_t)kx*144u;
                uint32_t bH  = sbase + OFF_B + kx*18432 + brq;
                uint32_t bL  = bH + 9216;
#pragma unroll 4
                for (int ks = 0; ks < nks; ks++) {
                    uint32_t ka = (uint32_t)(ks*16 + aseg*8)*2;
                    uint32_t kb = (uint32_t)(ks*16 + bseg*8)*2;
                    uint32_t a_h[4], a_l[4], b_h[2][4], b_l[2][4];
                    ldsm_x4(a_h, aH0 + ka);
                    if (full3) ldsm_x4(a_l, aL0 + ka);
                    ldsm_x4(b_h[0], bH + kb);
                    ldsm_x4(b_h[1], bH + 16*144 + kb);
                    ldsm_x4(b_l[0], bL + kb);
                    ldsm_x4(b_l[1], bL + 16*144 + kb);
#pragma unroll
                    for (int np = 0; np < 2; np++)
#pragma unroll
                        for (int sub = 0; sub < 2; sub++) {
                            int nt = np*2 + sub;
                            mma_bf16(acc[nt], a_h, &b_h[np][sub*2]);
                            mma_bf16(acc[nt], a_h, &b_l[np][sub*2]);
                            if (full3) mma_bf16(acc[nt], a_l, &b_h[np][sub*2]);
                        }
                }
            }
        }
    }

    int g = lane >> 2, tq = lane & 3;
    if (EPI == 0) {
        __syncthreads();    // all ldsm done before smem reuse
        uint32_t* OTH = (uint32_t*)sm;
        uint32_t* OTL = (uint32_t*)(sm + 9216);
#pragma unroll
        for (int nt = 0; nt < 4; nt++) {
            int cbase = warp_n*32 + nt*8 + tq*2;
            int c2 = cbase >> 1;
            float bv0 = bias[cbase], bv1 = bias[cbase + 1];
#pragma unroll
            for (int half = 0; half < 2; half++) {
                int px = warp_m*16 + g + half*8;
                float v0 = acc[nt][half*2]     + bv0;
                float v1 = acc[nt][half*2 + 1] + bv1;
                v0 = v0 >= 0.f ? v0 : 0.1f*v0;
                v1 = v1 >= 0.f ? v1 : 0.1f*v1;
                uint32_t u0 = pack_bf(v0), u1 = pack_bf(v1);
                OTH[px*36 + c2] = (u0 & 0xffffu) | (u1 << 16);
                OTL[px*36 + c2] = (u0 >> 16) | (u1 & 0xffff0000u);
            }
        }
        __syncthreads();
        for (int i = t; i < 512; i += 256) {
            int p = i >> 3, f = i & 7;
            size_t go = (((size_t)b*HW + y*WW + x0 + p) << 6) + (f << 3);
            *(float4*)(outh + go) = *(const float4*)((char*)OTH + p*144 + f*16);
            *(float4*)(outl + go) = *(const float4*)((char*)OTL + p*144 + f*16);
        }
    } else {
        float* dst = (float*)g_offm;
#pragma unroll
        for (int nt = 0; nt < 4; nt++)
#pragma unroll
            for (int rg = 0; rg < 4; rg++) {
                int px = warp_m*16 + g + ((rg >> 1) ? 8 : 0);
                int c  = nc*64 + warp_n*32 + nt*8 + tq*2 + (rg & 1);
                if (c >= COUTR) continue;
                int pix = y*WW + x0 + px;
                float v = acc[nt][rg] + bias[c];
                if (c < 288) {
                    int ch = c >> 1, comp = c & 1;
                    const float* fl = (c < 144) ? flow1 : flow2;
                    float add = fl[((size_t)b*2 + (1 - comp))*HW + pix];
                    dst[(((size_t)b*144 + ch)*HW + pix)*4 + comp] = 10.f*tanhf(v) + add;
                } else {
                    int ch = c - 288;
                    dst[(((size_t)b*144 + ch)*HW + pix)*4 + 2] = 1.f/(1.f + expf(-v));
                }
            }
    }
}

// ==================== dcn: smem-pipelined fp16 gather + HMMA + atomic reduce ====================
// Block: 256 thr, 64 px, 8 groups (half q), grid (256, BB, 2).
// Double-buffered cp.async prefetch of offm (9 KB) + weights (22 KB) per group.
__global__ __launch_bounds__(256) void dcn8_k(float* __restrict__ out)
{
    extern __shared__ char dsm[];
    const int OFF_OFFM = 0;          // 2 x 9216
    const int OFF_WH   = 18432;      // 2 x 11264
    const int OFF_WL   = 40960;      // 2 x 11264
    const int OFF_VAL  = 63488;      // 11264; total 74752

    uint32_t base = smem_u32(dsm);
    int p0 = blockIdx.x << 6, b = blockIdx.y, q = blockIdx.z;
    int t = threadIdx.x, lane = t & 31, wid = t >> 5;
    int warp_m = wid & 3, warp_n = wid >> 2;

    float acc[4][4];
#pragma unroll
    for (int i = 0; i < 4; i++)
#pragma unroll
        for (int j2 = 0; j2 < 4; j2++) acc[i][j2] = 0.f;

    __half* s_valT = (__half*)(dsm + OFF_VAL);
    // zero j-padding cols 72..87 (row stride 88 halves = 176 B)
    if (t < 128) {
        int p = t >> 1, f = t & 1;
        *(uint4*)(s_valT + p*88 + 72 + f*8) = make_uint4(0,0,0,0);
    }

    const float4* offm = g_offm + (size_t)b*144*HW;

    const uint32_t aRowOff = (uint32_t)(warp_m*16 + (lane & 15))*176u + (uint32_t)((lane >> 4)*8)*2u;
    const uint32_t bRow = base + OFF_VAL
                        + (uint32_t)(warp_n*32 + (lane & 7) + ((lane >> 4) & 1)*8)*176u
                        + (uint32_t)(((lane >> 3) & 1)*8)*2u;

    auto issue_grp = [&](int g1, int bufn) {
        for (int i = t; i < 576; i += 256) {
            int k = i >> 6, p = i & 63;
            const float4* s = offm + (size_t)(g1*9 + k)*HW + p0 + p;
            CP_ASYNC16(base + OFF_OFFM + bufn*9216 + i*16, s, 16u);
        }
        const char* sh = (const char*)(g_wth + (size_t)g1*5632);
        const char* sl = (const char*)(g_wtl + (size_t)g1*5632);
        for (int i = t; i < 704; i += 256) {
            CP_ASYNC16(base + OFF_WH + bufn*11264 + i*16, sh + i*16, 16u);
            CP_ASYNC16(base + OFF_WL + bufn*11264 + i*16, sl + i*16, 16u);
        }
        CP_COMMIT();
    };

    issue_grp(q*8, 0);
    int buf = 0;

    for (int gi = 0; gi < 8; gi++) {
        int g = q*8 + gi;
        CP_WAIT0();        // this thread's copies for group gi done
        __syncthreads();   // all threads' copies visible; prev GEMM done (s_valT, buf^1 free)
        if (gi < 7) issue_grp(g + 1, buf ^ 1);

        const float4* soff = (const float4*)(dsm + OFF_OFFM + buf*9216);
        const __half* gb = g_xt + ((size_t)(b*16 + g))*HW*8;
#pragma unroll
        for (int rep = 0; rep < 3; rep++) {
            int task = t + (rep << 8);
            if (task < 576) {
                int k = task >> 6, p = task & 63;
                int pix = p0 + p, y = pix >> 7, x = pix & 127;
                float4 om = soff[task];
                float m = om.z;
                float py = (float)(y + (k/3) - 1) + om.x;
                float px = (float)(x + (k%3) - 1) + om.y;
                float fy = floorf(py), fx = floorf(px);
                float wy = py - fy, wx = px - fx;
                int y0 = (int)fy, x0 = (int)fx, y1 = y0 + 1, x1 = x0 + 1;
                float vy0 = ((unsigned)y0 < HH) ? 1.f : 0.f;
                float vy1 = ((unsigned)y1 < HH) ? 1.f : 0.f;
                float vx0 = ((unsigned)x0 < WW) ? 1.f : 0.f;
                float vx1 = ((unsigned)x1 < WW) ? 1.f : 0.f;
                int y0c = min(max(y0,0),HH-1), y1c = min(max(y1,0),HH-1);
                int x0c = min(max(x0,0),WW-1), x1c = min(max(x1,0),WW-1);
                float w00 = (1.f-wy)*(1.f-wx)*m*vy0*vx0;
                float w01 = (1.f-wy)*wx      *m*vy0*vx1;
                float w10 = wy*(1.f-wx)      *m*vy1*vx0;
                float w11 = wy*wx            *m*vy1*vx1;
                uint4 r00 = *(const uint4*)(gb + ((size_t)(y0c*WW + x0c) << 3));
                uint4 r01 = *(const uint4*)(gb + ((size_t)(y0c*WW + x1c) << 3));
                uint4 r10 = *(const uint4*)(gb + ((size_t)(y1c*WW + x0c) << 3));
                uint4 r11 = *(const uint4*)(gb + ((size_t)(y1c*WW + x1c) << 3));
                const __half2* h00 = (const __half2*)&r00;
                const __half2* h01 = (const __half2*)&r01;
                const __half2* h10 = (const __half2*)&r10;
                const __half2* h11 = (const __half2*)&r11;
                __half2 outp2[4];
#pragma unroll
                for (int i = 0; i < 4; i++) {
                    float2 f00 = __half22float2(h00[i]);
                    float2 f01 = __half22float2(h01[i]);
                    float2 f10 = __half22float2(h10[i]);
                    float2 f11 = __half22float2(h11[i]);
                    float v0 = w00*f00.x + w01*f01.x + w10*f10.x + w11*f11.x;
                    float v1 = w00*f00.y + w01*f01.y + w10*f10.y + w11*f11.y;
                    outp2[i] = __floats2half2_rn(v0, v1);
                }
                *(uint4*)(s_valT + p*88 + k*8) = *(const uint4*)outp2;
            }
        }
        __syncthreads();

        uint32_t whB = base + OFF_WH + buf*11264 + aRowOff;
        uint32_t wlB = base + OFF_WL + buf*11264 + aRowOff;
#pragma unroll
        for (int ks = 0; ks < 5; ks++) {
            uint32_t kOff = (uint32_t)(ks*16)*2u;
            uint32_t a_h[4], a_l[4], bv[2][4];
            ldsm_x4(a_h, whB + kOff);
            ldsm_x4(a_l, wlB + kOff);
            ldsm_x4(bv[0], bRow + kOff);
            ldsm_x4(bv[1], bRow + 16*176 + kOff);
#pragma unroll
            for (int np = 0; np < 2; np++)
#pragma unroll
                for (int sub = 0; sub < 2; sub++) {
                    int nt = np*2 + sub;
                    mma_f16(acc[nt], a_h, &bv[np][sub*2]);
                    mma_f16(acc[nt], a_l, &bv[np][sub*2]);
                }
        }
        buf ^= 1;
    }

    float* pout = out + (size_t)b*64*HW;
    int gg = lane >> 2, tq = lane & 3;
#pragma unroll
    for (int nt = 0; nt < 4; nt++)
#pragma unroll
        for (int rg = 0; rg < 4; rg++) {
            int o = warp_m*16 + gg + ((rg >> 1) ? 8 : 0);
            int p = warp_n*32 + nt*8 + tq*2 + (rg & 1);
            atomicAdd(&pout[(size_t)o*HW + p0 + p], acc[nt][rg]);
        }
}

// ==================== launch ====================
extern "C" void kernel_launch(void* const* d_in, const int* in_sizes, int n_in,
                              void* d_out, int out_size)
{
    const float* x   = (const float*)d_in[0];
    const float* exf = (const float*)d_in[1];
    const float* f1  = (const float*)d_in[2];
    const float* f2  = (const float*)d_in[3];
    const float* w1  = (const float*)d_in[4];
    const float* b1  = (const float*)d_in[5];
    const float* w2  = (const float*)d_in[6];
    const float* b2  = (const float*)d_in[7];
    const float* w3  = (const float*)d_in[8];
    const float* b3  = (const float*)d_in[9];
    const float* w4  = (const float*)d_in[10];
    const float* b4  = (const float*)d_in[11];
    const float* dw  = (const float*)d_in[12];
    const float* db  = (const float*)d_in[13];
    float* out = (float*)d_out;

    uint16_t *p_i0h, *p_i0l, *p_h1h, *p_h1l, *p_h2h, *p_h2l, *p_h3h, *p_h3l;
    uint16_t *p_w1h, *p_w1l, *p_w2h, *p_w2l, *p_w3h, *p_w3l, *p_w4h, *p_w4l;
    cudaGetSymbolAddress((void**)&p_i0h, g_in0h); cudaGetSymbolAddress((void**)&p_i0l, g_in0l);
    cudaGetSymbolAddress((void**)&p_h1h, g_h1h);  cudaGetSymbolAddress((void**)&p_h1l, g_h1l);
    cudaGetSymbolAddress((void**)&p_h2h, g_h2h);  cudaGetSymbolAddress((void**)&p_h2l, g_h2l);
    cudaGetSymbolAddress((void**)&p_h3h, g_h3h);  cudaGetSymbolAddress((void**)&p_h3l, g_h3l);
    cudaGetSymbolAddress((void**)&p_w1h, g_w1h);  cudaGetSymbolAddress((void**)&p_w1l, g_w1l);
    cudaGetSymbolAddress((void**)&p_w2h, g_w2h);  cudaGetSymbolAddress((void**)&p_w2l, g_w2l);
    cudaGetSymbolAddress((void**)&p_w3h, g_w3h);  cudaGetSymbolAddress((void**)&p_w3l, g_w3l);
    cudaGetSymbolAddress((void**)&p_w4h, g_w4h);  cudaGetSymbolAddress((void**)&p_w4l, g_w4l);

    const int SMTOT = 57024 + 55296;   // 112320
    const int SMDCN = 74752;
    cudaFuncSetAttribute(convmma_k<196,64,64,0>,  cudaFuncAttributeMaxDynamicSharedMemorySize, SMTOT);
    cudaFuncSetAttribute(convmma_k<64,64,64,0>,   cudaFuncAttributeMaxDynamicSharedMemorySize, SMTOT);
    cudaFuncSetAttribute(convmma_k<64,448,432,1>, cudaFuncAttributeMaxDynamicSharedMemorySize, SMTOT);
    cudaFuncSetAttribute(dcn8_k, cudaFuncAttributeMaxDynamicSharedMemorySize, SMDCN);

    pack_in0_k<<<dim3(HW/64, 4, BB), 256>>>(exf, f1, f2);
    transp_x_k<<<dim3(HW/256, 16, BB), 256>>>(x);
    wdcn_k<<<(16*64*88 + 255)/256, 256>>>(dw);
    init_out_k<<<(BB*64*HW/4 + 255)/256, 256>>>(db, out);
    wprep_k<<<(36*64*72  + 255)/256, 256>>>(w1, 196, 64, 64, 36, p_w1h, p_w1l);
    wprep_k<<<(9*64*72   + 255)/256, 256>>>(w2,  64, 64, 64,  9, p_w2h, p_w2l);
    wprep_k<<<(9*64*72   + 255)/256, 256>>>(w3,  64, 64, 64,  9, p_w3h, p_w3l);
    wprep_k<<<(9*448*72  + 255)/256, 256>>>(w4,  64, 432, 448, 9, p_w4h, p_w4l);

    convmma_k<196,64,64,0> <<<dim3(BB*256, 1), 256, SMTOT>>>(p_i0h, p_i0l, p_w1h, p_w1l, b1, p_h1h, p_h1l, nullptr, nullptr);
    convmma_k<64,64,64,0>  <<<dim3(BB*256, 1), 256, SMTOT>>>(p_h1h, p_h1l, p_w2h, p_w2l, b2, p_h2h, p_h2l, nullptr, nullptr);
    convmma_k<64,64,64,0>  <<<dim3(BB*256, 1), 256, SMTOT>>>(p_h2h, p_h2l, p_w3h, p_w3l, b3, p_h3h, p_h3l, nullptr, nullptr);
    convmma_k<64,448,432,1><<<dim3(BB*256, 7), 256, SMTOT>>>(p_h3h, p_h3l, p_w4h, p_w4l, b4, nullptr, nullptr, f1, f2);

    dcn8_k<<<dim3(256, BB, 2), 256, SMDCN>>>(out);
}